// round 4
// baseline (speedup 1.0000x reference)
#include <cuda_runtime.h>
#include <cstdint>

#define N_NODES 100000
#define N_REL   4
#define N_EDGES 600000
#define D       128
#define KTOT    (N_REL * D)   // 512

// Scratch (device globals — no allocation allowed in kernel_launch)
__device__ float g_agg[(size_t)N_NODES * KTOT];      // [N, 512] concat per-relation agg
__device__ int   g_cnt[2 * N_REL * N_NODES];         // (r*2+io)*N + n ; io: 0=out(src),1=in(dst)
__device__ float g_rs [2 * N_REL * N_NODES];         // rsqrt(max(cnt,1))

// ---------------------------------------------------------------------------
// Degree histogram: one thread per (relation, edge), two int atomics.
__global__ void degree_kernel(const int* __restrict__ edges) {
    int i = blockIdx.x * blockDim.x + threadIdx.x;
    if (i >= N_REL * N_EDGES) return;
    int r = i / N_EDGES;
    int e = i - r * N_EDGES;
    int s = edges[(r * 2 + 0) * N_EDGES + e];
    int t = edges[(r * 2 + 1) * N_EDGES + e];
    atomicAdd(&g_cnt[(r * 2 + 0) * N_NODES + s], 1);
    atomicAdd(&g_cnt[(r * 2 + 1) * N_NODES + t], 1);
}

// rs = rsqrt(clip(deg, 1))
__global__ void rs_kernel() {
    int i = blockIdx.x * blockDim.x + threadIdx.x;
    if (i >= 2 * N_REL * N_NODES) return;
    g_rs[i] = rsqrtf(fmaxf((float)g_cnt[i], 1.0f));
}

// ---------------------------------------------------------------------------
// SpMM scatter: one warp per edge. Lane l handles float4 at column l*4.
// Fused normalization: contribution = X[src] * (rs_out[src] * rs_in[dst]).
// Vectorized reduction (red.global.add.v4.f32) into g_agg[dst][r*128 + ...].
__global__ void scatter_kernel(const int* __restrict__ edges,
                               const float* __restrict__ X) {
    int gtid = blockIdx.x * blockDim.x + threadIdx.x;
    int w = gtid >> 5;
    if (w >= N_REL * N_EDGES) return;
    int lane = threadIdx.x & 31;
    int r = w / N_EDGES;
    int e = w - r * N_EDGES;
    int s = __ldg(&edges[(r * 2 + 0) * N_EDGES + e]);
    int t = __ldg(&edges[(r * 2 + 1) * N_EDGES + e]);
    float coef = __ldg(&g_rs[(r * 2 + 0) * N_NODES + s]) *
                 __ldg(&g_rs[(r * 2 + 1) * N_NODES + t]);
    float4 x = __ldg(((const float4*)(X + (size_t)s * D)) + lane);
    float* dst = &g_agg[(size_t)t * KTOT + r * D + lane * 4];
    asm volatile("red.global.add.v4.f32 [%0], {%1, %2, %3, %4};"
                 :: "l"(dst),
                    "f"(x.x * coef), "f"(x.y * coef),
                    "f"(x.z * coef), "f"(x.w * coef)
                 : "memory");
}

// ---------------------------------------------------------------------------
// GEMM: C[M,128] = A[M,512] @ B[512,128], fp32.
// BM=64, BN=128, BK=16, 256 threads; each thread computes a 4x8 micro-tile.
#define BM 64
#define BN 128
#define BK 16

__global__ __launch_bounds__(256)
void gemm_kernel(const float* __restrict__ A, const float* __restrict__ B,
                 float* __restrict__ C) {
    __shared__ __align__(16) float As[BK][BM];   // A stored k-major (transposed)
    __shared__ __align__(16) float Bs[BK][BN];

    int tid  = threadIdx.x;
    int row0 = blockIdx.x * BM;
    int tx = tid & 15;    // 0..15 -> 8 cols each = 128
    int ty = tid >> 4;    // 0..15 -> 4 rows each = 64

    float acc[4][8];
#pragma unroll
    for (int i = 0; i < 4; i++)
#pragma unroll
        for (int j = 0; j < 8; j++) acc[i][j] = 0.0f;

    // Global-load coordinates for the A tile (64 x 16): one float4 per thread.
    int ar = tid >> 2;                        // 0..63
    int ak = (tid & 3) * 4;                   // 0,4,8,12
    int arow = min(row0 + ar, N_NODES - 1);   // clamp for last partial block

    for (int k0 = 0; k0 < KTOT; k0 += BK) {
        float4 a4 = *(const float4*)(A + (size_t)arow * KTOT + k0 + ak);
        As[ak + 0][ar] = a4.x;
        As[ak + 1][ar] = a4.y;
        As[ak + 2][ar] = a4.z;
        As[ak + 3][ar] = a4.w;

#pragma unroll
        for (int l = 0; l < 2; l++) {
            int j  = tid + l * 256;           // 0..511 float4s of the 16x128 tile
            int kk = j >> 5;
            int c4 = (j & 31) * 4;
            *(float4*)&Bs[kk][c4] =
                *(const float4*)(B + (size_t)(k0 + kk) * BN + c4);
        }
        __syncthreads();

#pragma unroll
        for (int kk = 0; kk < BK; kk++) {
            float4 a  = *(const float4*)&As[kk][ty * 4];
            float4 b0 = *(const float4*)&Bs[kk][tx * 8];
            float4 b1 = *(const float4*)&Bs[kk][tx * 8 + 4];
            float av[4] = {a.x, a.y, a.z, a.w};
            float bv[8] = {b0.x, b0.y, b0.z, b0.w, b1.x, b1.y, b1.z, b1.w};
#pragma unroll
            for (int i = 0; i < 4; i++)
#pragma unroll
                for (int j = 0; j < 8; j++)
                    acc[i][j] = fmaf(av[i], bv[j], acc[i][j]);
        }
        __syncthreads();
    }

#pragma unroll
    for (int i = 0; i < 4; i++) {
        int row = row0 + ty * 4 + i;
        if (row < N_NODES) {
            float4 c0 = make_float4(acc[i][0], acc[i][1], acc[i][2], acc[i][3]);
            float4 c1 = make_float4(acc[i][4], acc[i][5], acc[i][6], acc[i][7]);
            *(float4*)(C + (size_t)row * D + tx * 8)     = c0;
            *(float4*)(C + (size_t)row * D + tx * 8 + 4) = c1;
        }
    }
}

// ---------------------------------------------------------------------------
extern "C" void kernel_launch(void* const* d_in, const int* in_sizes, int n_in,
                              void* d_out, int out_size) {
    const int*   edges = (const int*)d_in[0];    // [4, 2, 600000] int32
    const float* X     = (const float*)d_in[1];  // [100000, 128] f32
    const float* W     = (const float*)d_in[2];  // [4, 128, 128] f32 == [512,128]
    float*       out   = (float*)d_out;          // [100000, 128] f32

    void* aggp = nullptr;
    void* cntp = nullptr;
    cudaGetSymbolAddress(&aggp, g_agg);
    cudaGetSymbolAddress(&cntp, g_cnt);

    cudaMemsetAsync(aggp, 0, sizeof(float) * (size_t)N_NODES * KTOT, 0);
    cudaMemsetAsync(cntp, 0, sizeof(int) * 2 * N_REL * N_NODES, 0);

    {
        int total = N_REL * N_EDGES;
        degree_kernel<<<(total + 255) / 256, 256>>>(edges);
    }
    {
        int total = 2 * N_REL * N_NODES;
        rs_kernel<<<(total + 255) / 256, 256>>>();
    }
    {
        // one warp per (relation, edge)
        long long warps = (long long)N_REL * N_EDGES;
        long long threads = warps * 32;
        int blocks = (int)((threads + 255) / 256);
        scatter_kernel<<<blocks, 256>>>(edges, X);
    }
    {
        int blocks = (N_NODES + BM - 1) / BM;
        float* aggf = nullptr;
        cudaGetSymbolAddress((void**)&aggf, g_agg);
        gemm_kernel<<<blocks, 256>>>(aggf, W, out);
    }
}

// round 5
// speedup vs baseline: 1.1530x; 1.1530x over previous
#include <cuda_runtime.h>
#include <cstdint>

#define N_NODES 100000
#define N_REL   4
#define N_EDGES 600000
#define D       128
#define KTOT    (N_REL * D)   // 512

// Scratch (device globals — no allocation allowed in kernel_launch)
__device__ float g_agg[(size_t)N_NODES * KTOT];      // [N, 512] concat per-relation agg
__device__ int   g_cnt[2 * N_REL * N_NODES];         // (r*2+io)*N + n ; io: 0=out(src),1=in(dst)
__device__ float g_rs [2 * N_REL * N_NODES];         // rsqrt(max(cnt,1))

// ---------------------------------------------------------------------------
// Degree histogram: one thread per (relation, edge), two int atomics.
__global__ void degree_kernel(const int* __restrict__ edges) {
    int i = blockIdx.x * blockDim.x + threadIdx.x;
    if (i >= N_REL * N_EDGES) return;
    int r = i / N_EDGES;
    int e = i - r * N_EDGES;
    int s = edges[(r * 2 + 0) * N_EDGES + e];
    int t = edges[(r * 2 + 1) * N_EDGES + e];
    atomicAdd(&g_cnt[(r * 2 + 0) * N_NODES + s], 1);
    atomicAdd(&g_cnt[(r * 2 + 1) * N_NODES + t], 1);
}

// rs = rsqrt(clip(deg, 1))
__global__ void rs_kernel() {
    int i = blockIdx.x * blockDim.x + threadIdx.x;
    if (i >= 2 * N_REL * N_NODES) return;
    g_rs[i] = rsqrtf(fmaxf((float)g_cnt[i], 1.0f));
}

// ---------------------------------------------------------------------------
// SpMM scatter: one warp per edge. Lane l handles float4 at column l*4.
// Fused normalization: contribution = X[src] * (rs_out[src] * rs_in[dst]).
// Vectorized reduction (red.global.add.v4.f32) into g_agg[dst][r*128 + ...].
__global__ void scatter_kernel(const int* __restrict__ edges,
                               const float* __restrict__ X) {
    int gtid = blockIdx.x * blockDim.x + threadIdx.x;
    int w = gtid >> 5;
    if (w >= N_REL * N_EDGES) return;
    int lane = threadIdx.x & 31;
    int r = w / N_EDGES;
    int e = w - r * N_EDGES;
    int s = __ldg(&edges[(r * 2 + 0) * N_EDGES + e]);
    int t = __ldg(&edges[(r * 2 + 1) * N_EDGES + e]);
    float coef = __ldg(&g_rs[(r * 2 + 0) * N_NODES + s]) *
                 __ldg(&g_rs[(r * 2 + 1) * N_NODES + t]);
    float4 x = __ldg(((const float4*)(X + (size_t)s * D)) + lane);
    float* dst = &g_agg[(size_t)t * KTOT + r * D + lane * 4];
    asm volatile("red.global.add.v4.f32 [%0], {%1, %2, %3, %4};"
                 :: "l"(dst),
                    "f"(x.x * coef), "f"(x.y * coef),
                    "f"(x.z * coef), "f"(x.w * coef)
                 : "memory");
}

// ---------------------------------------------------------------------------
// TF32 tensor-core GEMM: C[M,128] = A[M,512] @ B[512,128].
// BM=128, BN=128, BK=32. 256 threads = 8 warps in a 2(M) x 4(N) grid;
// each warp owns a 64x32 tile = 4x4 grid of m16n8k8 mma accumulators.
// Operands converted with cvt.rna.tf32.f32 (round-to-nearest) at staging.
#define GBM 128
#define GBN 128
#define GBK 32
#define AS_STRIDE 36    // a-frag banks: (4*lg + lt) % 32 -> all 32 distinct
#define BS_STRIDE 136   // b-frag banks: (lg + 8*lt) % 32 -> all 32 distinct

__device__ __forceinline__ uint32_t f2tf32(float f) {
    uint32_t u;
    asm("cvt.rna.tf32.f32 %0, %1;" : "=r"(u) : "f"(f));
    return u;
}

__device__ __forceinline__ void mma_tf32(float* d, const uint32_t* a,
                                         const uint32_t* b) {
    asm volatile(
        "mma.sync.aligned.m16n8k8.row.col.f32.tf32.tf32.f32 "
        "{%0,%1,%2,%3}, {%4,%5,%6,%7}, {%8,%9}, {%0,%1,%2,%3};"
        : "+f"(d[0]), "+f"(d[1]), "+f"(d[2]), "+f"(d[3])
        : "r"(a[0]), "r"(a[1]), "r"(a[2]), "r"(a[3]), "r"(b[0]), "r"(b[1]));
}

__global__ __launch_bounds__(256, 2)
void gemm_tf32_kernel(const float* __restrict__ A, const float* __restrict__ B,
                      float* __restrict__ C) {
    __shared__ uint32_t As[GBM][AS_STRIDE];
    __shared__ uint32_t Bs[GBK][BS_STRIDE];

    int tid  = threadIdx.x;
    int wid  = tid >> 5;
    int lane = tid & 31;
    int lg   = lane >> 2;     // 0..7
    int lt   = lane & 3;      // 0..3
    int warp_m = wid & 1;     // 0..1 -> 64-row slab
    int warp_n = wid >> 1;    // 0..3 -> 32-col slab
    int row0 = blockIdx.x * GBM;

    float acc[4][4][4];
#pragma unroll
    for (int mi = 0; mi < 4; mi++)
#pragma unroll
        for (int ni = 0; ni < 4; ni++)
#pragma unroll
            for (int j = 0; j < 4; j++) acc[mi][ni][j] = 0.0f;

    // Staging coordinates:
    // A tile (128x32): thread row = tid>>1, 16 floats at col (tid&1)*16.
    int s_ar = tid >> 1;
    int s_ac = (tid & 1) * 16;
    int g_ar = min(row0 + s_ar, N_NODES - 1);   // clamp last partial block
    // B tile (32x128): thread row = tid>>3, 16 floats at col (tid&7)*16.
    int s_br = tid >> 3;
    int s_bc = (tid & 7) * 16;

    for (int k0 = 0; k0 < KTOT; k0 += GBK) {
        // ---- stage A (convert to tf32-rna) ----
        const float4* ag =
            (const float4*)(A + (size_t)g_ar * KTOT + k0 + s_ac);
#pragma unroll
        for (int i = 0; i < 4; i++) {
            float4 v = __ldg(ag + i);
            As[s_ar][s_ac + i * 4 + 0] = f2tf32(v.x);
            As[s_ar][s_ac + i * 4 + 1] = f2tf32(v.y);
            As[s_ar][s_ac + i * 4 + 2] = f2tf32(v.z);
            As[s_ar][s_ac + i * 4 + 3] = f2tf32(v.w);
        }
        // ---- stage B ----
        const float4* bg =
            (const float4*)(B + (size_t)(k0 + s_br) * GBN + s_bc);
#pragma unroll
        for (int i = 0; i < 4; i++) {
            float4 v = __ldg(bg + i);
            Bs[s_br][s_bc + i * 4 + 0] = f2tf32(v.x);
            Bs[s_br][s_bc + i * 4 + 1] = f2tf32(v.y);
            Bs[s_br][s_bc + i * 4 + 2] = f2tf32(v.z);
            Bs[s_br][s_bc + i * 4 + 3] = f2tf32(v.w);
        }
        __syncthreads();

#pragma unroll
        for (int ks = 0; ks < GBK; ks += 8) {
            uint32_t af[4][4];
            uint32_t bf[4][2];
#pragma unroll
            for (int mi = 0; mi < 4; mi++) {
                int base = warp_m * 64 + mi * 16;
                af[mi][0] = As[base + lg    ][ks + lt    ];
                af[mi][1] = As[base + lg + 8][ks + lt    ];
                af[mi][2] = As[base + lg    ][ks + lt + 4];
                af[mi][3] = As[base + lg + 8][ks + lt + 4];
            }
#pragma unroll
            for (int ni = 0; ni < 4; ni++) {
                int col = warp_n * 32 + ni * 8 + lg;
                bf[ni][0] = Bs[ks + lt    ][col];
                bf[ni][1] = Bs[ks + lt + 4][col];
            }
#pragma unroll
            for (int mi = 0; mi < 4; mi++)
#pragma unroll
                for (int ni = 0; ni < 4; ni++)
                    mma_tf32(acc[mi][ni], af[mi], bf[ni]);
        }
        __syncthreads();
    }

    // ---- epilogue: c0,c1 -> (row, 2*lt), (row, 2*lt+1); c2,c3 -> row+8 ----
#pragma unroll
    for (int mi = 0; mi < 4; mi++) {
#pragma unroll
        for (int ni = 0; ni < 4; ni++) {
            int r = row0 + warp_m * 64 + mi * 16 + lg;
            int c = warp_n * 32 + ni * 8 + 2 * lt;
            if (r < N_NODES) {
                float2 v = make_float2(acc[mi][ni][0], acc[mi][ni][1]);
                *(float2*)(C + (size_t)r * D + c) = v;
            }
            if (r + 8 < N_NODES) {
                float2 v = make_float2(acc[mi][ni][2], acc[mi][ni][3]);
                *(float2*)(C + (size_t)(r + 8) * D + c) = v;
            }
        }
    }
}

// ---------------------------------------------------------------------------
extern "C" void kernel_launch(void* const* d_in, const int* in_sizes, int n_in,
                              void* d_out, int out_size) {
    const int*   edges = (const int*)d_in[0];    // [4, 2, 600000] int32
    const float* X     = (const float*)d_in[1];  // [100000, 128] f32
    const float* W     = (const float*)d_in[2];  // [4, 128, 128] f32 == [512,128]
    float*       out   = (float*)d_out;          // [100000, 128] f32

    void* aggp = nullptr;
    void* cntp = nullptr;
    cudaGetSymbolAddress(&aggp, g_agg);
    cudaGetSymbolAddress(&cntp, g_cnt);

    cudaMemsetAsync(aggp, 0, sizeof(float) * (size_t)N_NODES * KTOT, 0);
    cudaMemsetAsync(cntp, 0, sizeof(int) * 2 * N_REL * N_NODES, 0);

    {
        int total = N_REL * N_EDGES;
        degree_kernel<<<(total + 255) / 256, 256>>>(edges);
    }
    {
        int total = 2 * N_REL * N_NODES;
        rs_kernel<<<(total + 255) / 256, 256>>>();
    }
    {
        // one warp per (relation, edge)
        long long warps = (long long)N_REL * N_EDGES;
        long long threads = warps * 32;
        int blocks = (int)((threads + 255) / 256);
        scatter_kernel<<<blocks, 256>>>(edges, X);
    }
    {
        int blocks = (N_NODES + GBM - 1) / GBM;   // 782
        gemm_tf32_kernel<<<blocks, 256>>>((const float*)aggp, W, out);
    }
}

// round 6
// speedup vs baseline: 1.7022x; 1.4763x over previous
#include <cuda_runtime.h>
#include <cuda_fp16.h>
#include <cstdint>

#define N_NODES 100000
#define N_REL   4
#define N_EDGES 600000
#define D       128
#define KTOT    (N_REL * D)   // 512

// Scratch (device globals — no allocation allowed in kernel_launch)
__device__ __half g_Y[(size_t)N_NODES * KTOT];       // [N, 4, 128] fp16: rs_out*(X@W_r)
__device__ int    g_cnt[2 * N_REL * N_NODES];        // (r*2+io)*N + n ; io: 0=out(src),1=in(dst)
__device__ float  g_rs [2 * N_REL * N_NODES];        // rsqrt(max(cnt,1))

// ---------------------------------------------------------------------------
// Degree histogram: one thread per (relation, edge), two int atomics.
__global__ void degree_kernel(const int* __restrict__ edges) {
    int i = blockIdx.x * blockDim.x + threadIdx.x;
    if (i >= N_REL * N_EDGES) return;
    int r = i / N_EDGES;
    int e = i - r * N_EDGES;
    int s = edges[(r * 2 + 0) * N_EDGES + e];
    int t = edges[(r * 2 + 1) * N_EDGES + e];
    atomicAdd(&g_cnt[(r * 2 + 0) * N_NODES + s], 1);
    atomicAdd(&g_cnt[(r * 2 + 1) * N_NODES + t], 1);
}

// rs = rsqrt(clip(deg, 1))
__global__ void rs_kernel() {
    int i = blockIdx.x * blockDim.x + threadIdx.x;
    if (i >= 2 * N_REL * N_NODES) return;
    g_rs[i] = rsqrtf(fmaxf((float)g_cnt[i], 1.0f));
}

// ---------------------------------------------------------------------------
// TF32 tensor-core GEMM producing Y' = rs_out_r * (X @ W_r), stored fp16.
// C-block: 128 rows x 128 cols; grid.y = relation. K = 128.
// 256 threads = 8 warps (2 M x 4 N), warp tile 64x32, m16n8k8 tf32 mma.
#define GBM 128
#define GBN 128
#define GBK 32
#define AS_STRIDE 36    // words; 144 B row stride (16B aligned)
#define BS_STRIDE 136   // words; 544 B row stride (16B aligned)

__device__ __forceinline__ uint32_t f2tf32(float f) {
    uint32_t u;
    asm("cvt.rna.tf32.f32 %0, %1;" : "=r"(u) : "f"(f));
    return u;
}

__device__ __forceinline__ void mma_tf32(float* d, const uint32_t* a,
                                         const uint32_t* b) {
    asm volatile(
        "mma.sync.aligned.m16n8k8.row.col.f32.tf32.tf32.f32 "
        "{%0,%1,%2,%3}, {%4,%5,%6,%7}, {%8,%9}, {%0,%1,%2,%3};"
        : "+f"(d[0]), "+f"(d[1]), "+f"(d[2]), "+f"(d[3])
        : "r"(a[0]), "r"(a[1]), "r"(a[2]), "r"(a[3]), "r"(b[0]), "r"(b[1]));
}

__global__ __launch_bounds__(256, 2)
void gemm_tf32_kernel(const float* __restrict__ X, const float* __restrict__ W,
                      __half* __restrict__ Y) {
    __shared__ __align__(16) uint32_t As[GBM][AS_STRIDE];
    __shared__ __align__(16) uint32_t Bs[GBK][BS_STRIDE];

    int tid  = threadIdx.x;
    int wid  = tid >> 5;
    int lane = tid & 31;
    int lg   = lane >> 2;     // 0..7
    int lt   = lane & 3;      // 0..3
    int warp_m = wid & 1;     // 0..1 -> 64-row slab
    int warp_n = wid >> 1;    // 0..3 -> 32-col slab
    int row0 = blockIdx.x * GBM;
    int rel  = blockIdx.y;                      // relation index
    const float* B = W + (size_t)rel * (D * D); // W[rel], [128 k][128 j] row-major

    float acc[4][4][4];
#pragma unroll
    for (int mi = 0; mi < 4; mi++)
#pragma unroll
        for (int ni = 0; ni < 4; ni++)
#pragma unroll
            for (int j = 0; j < 4; j++) acc[mi][ni][j] = 0.0f;

    // Staging coords: A tile (128x32): row = tid>>1, 16 floats at col (tid&1)*16.
    int s_ar = tid >> 1;
    int s_ac = (tid & 1) * 16;
    int g_ar = min(row0 + s_ar, N_NODES - 1);
    // B tile (32x128): row = tid>>3, 16 floats at col (tid&7)*16.
    int s_br = tid >> 3;
    int s_bc = (tid & 7) * 16;

    for (int k0 = 0; k0 < D; k0 += GBK) {
        // ---- stage A (X rows), convert tf32-rna, vectorized STS.128 ----
        const float4* ag = (const float4*)(X + (size_t)g_ar * D + k0 + s_ac);
#pragma unroll
        for (int i = 0; i < 4; i++) {
            float4 v = __ldg(ag + i);
            uint4 u = make_uint4(f2tf32(v.x), f2tf32(v.y), f2tf32(v.z), f2tf32(v.w));
            *(uint4*)&As[s_ar][s_ac + i * 4] = u;
        }
        // ---- stage B (W[rel] rows) ----
        const float4* bg = (const float4*)(B + (size_t)(k0 + s_br) * GBN + s_bc);
#pragma unroll
        for (int i = 0; i < 4; i++) {
            float4 v = __ldg(bg + i);
            uint4 u = make_uint4(f2tf32(v.x), f2tf32(v.y), f2tf32(v.z), f2tf32(v.w));
            *(uint4*)&Bs[s_br][s_bc + i * 4] = u;
        }
        __syncthreads();

#pragma unroll
        for (int ks = 0; ks < GBK; ks += 8) {
            uint32_t af[4][4];
            uint32_t bf[4][2];
#pragma unroll
            for (int mi = 0; mi < 4; mi++) {
                int base = warp_m * 64 + mi * 16;
                af[mi][0] = As[base + lg    ][ks + lt    ];
                af[mi][1] = As[base + lg + 8][ks + lt    ];
                af[mi][2] = As[base + lg    ][ks + lt + 4];
                af[mi][3] = As[base + lg + 8][ks + lt + 4];
            }
#pragma unroll
            for (int ni = 0; ni < 4; ni++) {
                int col = warp_n * 32 + ni * 8 + lg;
                bf[ni][0] = Bs[ks + lt    ][col];
                bf[ni][1] = Bs[ks + lt + 4][col];
            }
#pragma unroll
            for (int mi = 0; mi < 4; mi++)
#pragma unroll
                for (int ni = 0; ni < 4; ni++)
                    mma_tf32(acc[mi][ni], af[mi], bf[ni]);
        }
        __syncthreads();
    }

    // ---- epilogue: scale by rs_out_rel[row], convert fp16, store to Y ----
    // c0,c1 -> (row, 2lt), (row, 2lt+1); c2,c3 -> row+8.
    const float* rs_out = g_rs + (size_t)(rel * 2 + 0) * N_NODES;
#pragma unroll
    for (int mi = 0; mi < 4; mi++) {
        int r = row0 + warp_m * 64 + mi * 16 + lg;
        float s0 = (r     < N_NODES) ? __ldg(&rs_out[r])     : 0.0f;
        float s1 = (r + 8 < N_NODES) ? __ldg(&rs_out[r + 8]) : 0.0f;
#pragma unroll
        for (int ni = 0; ni < 4; ni++) {
            int c = warp_n * 32 + ni * 8 + 2 * lt;
            if (r < N_NODES) {
                __half2 h = __floats2half2_rn(acc[mi][ni][0] * s0,
                                              acc[mi][ni][1] * s0);
                *(__half2*)(Y + (size_t)r * KTOT + rel * D + c) = h;
            }
            if (r + 8 < N_NODES) {
                __half2 h = __floats2half2_rn(acc[mi][ni][2] * s1,
                                              acc[mi][ni][3] * s1);
                *(__half2*)(Y + (size_t)(r + 8) * KTOT + rel * D + c) = h;
            }
        }
    }
}

// ---------------------------------------------------------------------------
// Scatter: one warp per (relation, edge). Lane l handles cols 4l..4l+3.
// out[t] += rs_in_r[t] * Y'[s, r, :]   (rs_out already folded into Y').
// Gather 8 B fp16 per lane; red.global.add.v4.f32 into d_out (51 MB, L2-hot).
__global__ void scatter_kernel(const int* __restrict__ edges,
                               const __half* __restrict__ Y,
                               float* __restrict__ out) {
    int gtid = blockIdx.x * blockDim.x + threadIdx.x;
    int w = gtid >> 5;
    if (w >= N_REL * N_EDGES) return;
    int lane = threadIdx.x & 31;
    int r = w / N_EDGES;
    int e = w - r * N_EDGES;
    int s = __ldg(&edges[(r * 2 + 0) * N_EDGES + e]);
    int t = __ldg(&edges[(r * 2 + 1) * N_EDGES + e]);
    float coef = __ldg(&g_rs[(r * 2 + 1) * N_NODES + t]);

    const uint2* yp = (const uint2*)(Y + (size_t)s * KTOT + r * D) + lane;
    uint2 v = __ldg(yp);
    __half2 h0 = *(__half2*)&v.x;
    __half2 h1 = *(__half2*)&v.y;
    float2 f0 = __half22float2(h0);
    float2 f1 = __half22float2(h1);

    float* dst = out + (size_t)t * D + lane * 4;
    asm volatile("red.global.add.v4.f32 [%0], {%1, %2, %3, %4};"
                 :: "l"(dst),
                    "f"(f0.x * coef), "f"(f0.y * coef),
                    "f"(f1.x * coef), "f"(f1.y * coef)
                 : "memory");
}

// ---------------------------------------------------------------------------
extern "C" void kernel_launch(void* const* d_in, const int* in_sizes, int n_in,
                              void* d_out, int out_size) {
    const int*   edges = (const int*)d_in[0];    // [4, 2, 600000] int32
    const float* X     = (const float*)d_in[1];  // [100000, 128] f32
    const float* W     = (const float*)d_in[2];  // [4, 128, 128] f32
    float*       out   = (float*)d_out;          // [100000, 128] f32

    void* cntp = nullptr;
    void* yp   = nullptr;
    cudaGetSymbolAddress(&cntp, g_cnt);
    cudaGetSymbolAddress(&yp, g_Y);

    cudaMemsetAsync(cntp, 0, sizeof(int) * 2 * N_REL * N_NODES, 0);
    cudaMemsetAsync(out, 0, sizeof(float) * (size_t)N_NODES * D, 0);

    {
        int total = N_REL * N_EDGES;
        degree_kernel<<<(total + 255) / 256, 256>>>(edges);
    }
    {
        int total = 2 * N_REL * N_NODES;
        rs_kernel<<<(total + 255) / 256, 256>>>();
    }
    {
        dim3 grid((N_NODES + GBM - 1) / GBM, N_REL);   // (782, 4)
        gemm_tf32_kernel<<<grid, 256>>>(X, W, (__half*)yp);
    }
    {
        // one warp per (relation, edge)
        long long warps = (long long)N_REL * N_EDGES;
        long long threads = warps * 32;
        int blocks = (int)((threads + 255) / 256);
        scatter_kernel<<<blocks, 256>>>(edges, (const __half*)yp, out);
    }
}

// round 7
// speedup vs baseline: 2.1136x; 1.2417x over previous
#include <cuda_runtime.h>
#include <cuda_fp16.h>
#include <cstdint>

#define N_NODES 100000
#define N_REL   4
#define N_EDGES 600000
#define D       128
#define KTOT    (N_REL * D)   // 512

// Scratch (device globals — no allocation allowed in kernel_launch)
__device__ __half g_Y[(size_t)N_NODES * KTOT];       // [N, 4, 128] fp16: rs_out*(X@W_r)
__device__ int    g_cnt[2 * N_REL * N_NODES];        // (r*2+io)*N + n ; io: 0=out(src),1=in(dst)
__device__ float  g_rs [2 * N_REL * N_NODES];        // rsqrt(max(cnt,1))

// ---------------------------------------------------------------------------
// Degree histogram: one thread per (relation, edge), two int atomics.
__global__ void degree_kernel(const int* __restrict__ edges) {
    int i = blockIdx.x * blockDim.x + threadIdx.x;
    if (i >= N_REL * N_EDGES) return;
    int r = i / N_EDGES;
    int e = i - r * N_EDGES;
    int s = edges[(r * 2 + 0) * N_EDGES + e];
    int t = edges[(r * 2 + 1) * N_EDGES + e];
    atomicAdd(&g_cnt[(r * 2 + 0) * N_NODES + s], 1);
    atomicAdd(&g_cnt[(r * 2 + 1) * N_NODES + t], 1);
}

// rs = rsqrt(clip(deg, 1))
__global__ void rs_kernel() {
    int i = blockIdx.x * blockDim.x + threadIdx.x;
    if (i >= 2 * N_REL * N_NODES) return;
    g_rs[i] = rsqrtf(fmaxf((float)g_cnt[i], 1.0f));
}

// ---------------------------------------------------------------------------
// TF32 tensor-core GEMM producing Y' = rs_out_r * (X @ W_r), stored fp16.
// C-block: 128 rows x 128 cols; grid.y = relation. K = 128.
// 256 threads = 8 warps (2 M x 4 N), warp tile 64x32, m16n8k8 tf32 mma.
#define GBM 128
#define GBN 128
#define GBK 32
#define AS_STRIDE 36    // words; 144 B row stride (16B aligned)
#define BS_STRIDE 136   // words; 544 B row stride (16B aligned)

__device__ __forceinline__ uint32_t f2tf32(float f) {
    uint32_t u;
    asm("cvt.rna.tf32.f32 %0, %1;" : "=r"(u) : "f"(f));
    return u;
}

__device__ __forceinline__ void mma_tf32(float* d, const uint32_t* a,
                                         const uint32_t* b) {
    asm volatile(
        "mma.sync.aligned.m16n8k8.row.col.f32.tf32.tf32.f32 "
        "{%0,%1,%2,%3}, {%4,%5,%6,%7}, {%8,%9}, {%0,%1,%2,%3};"
        : "+f"(d[0]), "+f"(d[1]), "+f"(d[2]), "+f"(d[3])
        : "r"(a[0]), "r"(a[1]), "r"(a[2]), "r"(a[3]), "r"(b[0]), "r"(b[1]));
}

__global__ __launch_bounds__(256, 2)
void gemm_tf32_kernel(const float* __restrict__ X, const float* __restrict__ W,
                      __half* __restrict__ Y) {
    __shared__ __align__(16) uint32_t As[GBM][AS_STRIDE];
    __shared__ __align__(16) uint32_t Bs[GBK][BS_STRIDE];

    int tid  = threadIdx.x;
    int wid  = tid >> 5;
    int lane = tid & 31;
    int lg   = lane >> 2;     // 0..7
    int lt   = lane & 3;      // 0..3
    int warp_m = wid & 1;     // 0..1 -> 64-row slab
    int warp_n = wid >> 1;    // 0..3 -> 32-col slab
    int row0 = blockIdx.x * GBM;
    int rel  = blockIdx.y;                      // relation index
    const float* B = W + (size_t)rel * (D * D); // W[rel], [128 k][128 j] row-major

    float acc[4][4][4];
#pragma unroll
    for (int mi = 0; mi < 4; mi++)
#pragma unroll
        for (int ni = 0; ni < 4; ni++)
#pragma unroll
            for (int j = 0; j < 4; j++) acc[mi][ni][j] = 0.0f;

    // Staging coords: A tile (128x32): row = tid>>1, 16 floats at col (tid&1)*16.
    int s_ar = tid >> 1;
    int s_ac = (tid & 1) * 16;
    int g_ar = min(row0 + s_ar, N_NODES - 1);
    // B tile (32x128): row = tid>>3, 16 floats at col (tid&7)*16.
    int s_br = tid >> 3;
    int s_bc = (tid & 7) * 16;

    for (int k0 = 0; k0 < D; k0 += GBK) {
        // ---- stage A (X rows), convert tf32-rna, vectorized STS.128 ----
        const float4* ag = (const float4*)(X + (size_t)g_ar * D + k0 + s_ac);
#pragma unroll
        for (int i = 0; i < 4; i++) {
            float4 v = __ldg(ag + i);
            uint4 u = make_uint4(f2tf32(v.x), f2tf32(v.y), f2tf32(v.z), f2tf32(v.w));
            *(uint4*)&As[s_ar][s_ac + i * 4] = u;
        }
        // ---- stage B (W[rel] rows) ----
        const float4* bg = (const float4*)(B + (size_t)(k0 + s_br) * GBN + s_bc);
#pragma unroll
        for (int i = 0; i < 4; i++) {
            float4 v = __ldg(bg + i);
            uint4 u = make_uint4(f2tf32(v.x), f2tf32(v.y), f2tf32(v.z), f2tf32(v.w));
            *(uint4*)&Bs[s_br][s_bc + i * 4] = u;
        }
        __syncthreads();

#pragma unroll
        for (int ks = 0; ks < GBK; ks += 8) {
            uint32_t af[4][4];
            uint32_t bf[4][2];
#pragma unroll
            for (int mi = 0; mi < 4; mi++) {
                int base = warp_m * 64 + mi * 16;
                af[mi][0] = As[base + lg    ][ks + lt    ];
                af[mi][1] = As[base + lg + 8][ks + lt    ];
                af[mi][2] = As[base + lg    ][ks + lt + 4];
                af[mi][3] = As[base + lg + 8][ks + lt + 4];
            }
#pragma unroll
            for (int ni = 0; ni < 4; ni++) {
                int col = warp_n * 32 + ni * 8 + lg;
                bf[ni][0] = Bs[ks + lt    ][col];
                bf[ni][1] = Bs[ks + lt + 4][col];
            }
#pragma unroll
            for (int mi = 0; mi < 4; mi++)
#pragma unroll
                for (int ni = 0; ni < 4; ni++)
                    mma_tf32(acc[mi][ni], af[mi], bf[ni]);
        }
        __syncthreads();
    }

    // ---- epilogue: scale by rs_out_rel[row], convert fp16, store to Y ----
    // c0,c1 -> (row, 2lt), (row, 2lt+1); c2,c3 -> row+8.
    const float* rs_out = g_rs + (size_t)(rel * 2 + 0) * N_NODES;
#pragma unroll
    for (int mi = 0; mi < 4; mi++) {
        int r = row0 + warp_m * 64 + mi * 16 + lg;
        float s0 = (r     < N_NODES) ? __ldg(&rs_out[r])     : 0.0f;
        float s1 = (r + 8 < N_NODES) ? __ldg(&rs_out[r + 8]) : 0.0f;
#pragma unroll
        for (int ni = 0; ni < 4; ni++) {
            int c = warp_n * 32 + ni * 8 + 2 * lt;
            if (r < N_NODES) {
                __half2 h = __floats2half2_rn(acc[mi][ni][0] * s0,
                                              acc[mi][ni][1] * s0);
                *(__half2*)(Y + (size_t)r * KTOT + rel * D + c) = h;
            }
            if (r + 8 < N_NODES) {
                __half2 h = __floats2half2_rn(acc[mi][ni][2] * s1,
                                              acc[mi][ni][3] * s1);
                *(__half2*)(Y + (size_t)(r + 8) * KTOT + rel * D + c) = h;
            }
        }
    }
}

// ---------------------------------------------------------------------------
// Scatter, warp-batched: each warp owns 32 consecutive edges of one relation.
// Phase 1 (coalesced): lane l loads (s, t) for edge base+l and coef=rs_in[t].
// Phase 2: loop over the 32 edges; s/t/coef broadcast via shfl; all 32 lanes
// gather 8 B of the fp16 Y row and issue red.global.add.v4.f32 into d_out.
// The 32 gathers are independent -> deep MLP, hides L2 latency.
// N_EDGES % 32 == 0, so there is no tail.
#define EDGES_PER_WARP 32
#define WARPS_PER_REL  (N_EDGES / EDGES_PER_WARP)   // 18750

__global__ __launch_bounds__(256)
void scatter_kernel(const int* __restrict__ edges,
                    const __half* __restrict__ Y,
                    float* __restrict__ out) {
    int gtid = blockIdx.x * blockDim.x + threadIdx.x;
    int warp = gtid >> 5;
    if (warp >= N_REL * WARPS_PER_REL) return;
    int lane = threadIdx.x & 31;
    int r  = warp / WARPS_PER_REL;
    int e0 = (warp - r * WARPS_PER_REL) * EDGES_PER_WARP;
    int e  = e0 + lane;

    // Coalesced per-lane edge metadata.
    int   s_l = __ldg(&edges[(r * 2 + 0) * N_EDGES + e]);
    int   t_l = __ldg(&edges[(r * 2 + 1) * N_EDGES + e]);
    float c_l = __ldg(&g_rs[(r * 2 + 1) * N_NODES + t_l]);

    const __half* Yr = Y + (size_t)r * D;   // relation offset within a Y row

#pragma unroll
    for (int i = 0; i < EDGES_PER_WARP; i++) {
        int   si = __shfl_sync(0xffffffffu, s_l, i);
        int   ti = __shfl_sync(0xffffffffu, t_l, i);
        float ci = __shfl_sync(0xffffffffu, c_l, i);

        uint2 v = __ldg((const uint2*)(Yr + (size_t)si * KTOT) + lane);
        float2 f0 = __half22float2(*(__half2*)&v.x);
        float2 f1 = __half22float2(*(__half2*)&v.y);

        float* dst = out + (size_t)ti * D + lane * 4;
        asm volatile("red.global.add.v4.f32 [%0], {%1, %2, %3, %4};"
                     :: "l"(dst),
                        "f"(f0.x * ci), "f"(f0.y * ci),
                        "f"(f1.x * ci), "f"(f1.y * ci)
                     : "memory");
    }
}

// ---------------------------------------------------------------------------
extern "C" void kernel_launch(void* const* d_in, const int* in_sizes, int n_in,
                              void* d_out, int out_size) {
    const int*   edges = (const int*)d_in[0];    // [4, 2, 600000] int32
    const float* X     = (const float*)d_in[1];  // [100000, 128] f32
    const float* W     = (const float*)d_in[2];  // [4, 128, 128] f32
    float*       out   = (float*)d_out;          // [100000, 128] f32

    void* cntp = nullptr;
    void* yp   = nullptr;
    cudaGetSymbolAddress(&cntp, g_cnt);
    cudaGetSymbolAddress(&yp, g_Y);

    cudaMemsetAsync(cntp, 0, sizeof(int) * 2 * N_REL * N_NODES, 0);
    cudaMemsetAsync(out, 0, sizeof(float) * (size_t)N_NODES * D, 0);

    {
        int total = N_REL * N_EDGES;
        degree_kernel<<<(total + 255) / 256, 256>>>(edges);
    }
    {
        int total = 2 * N_REL * N_NODES;
        rs_kernel<<<(total + 255) / 256, 256>>>();
    }
    {
        dim3 grid((N_NODES + GBM - 1) / GBM, N_REL);   // (782, 4)
        gemm_tf32_kernel<<<grid, 256>>>(X, W, (__half*)yp);
    }
    {
        // one warp per 32 edges of one relation
        int total_warps = N_REL * WARPS_PER_REL;       // 75000
        long long threads = (long long)total_warps * 32;
        int blocks = (int)((threads + 255) / 256);
        scatter_kernel<<<blocks, 256>>>(edges, (const __half*)yp, out);
    }
}

// round 8
// speedup vs baseline: 2.4769x; 1.1719x over previous
#include <cuda_runtime.h>
#include <cuda_fp16.h>
#include <cstdint>

#define N_NODES 100000
#define N_REL   4
#define N_EDGES 600000
#define D       128
#define KTOT    (N_REL * D)   // 512

// Scratch (device globals — no allocation allowed in kernel_launch)
__device__ __half g_Y [(size_t)N_NODES * KTOT];      // [N, 4, 128] fp16: rs_out*(X@W_r)
__device__ __half g_Xh[(size_t)N_NODES * D];         // X in fp16
__device__ __half g_Wt[(size_t)N_REL * D * D];       // W[r] transposed: [r][n][k] fp16
__device__ int    g_cnt[2 * N_REL * N_NODES];        // (r*2+io)*N + n ; io: 0=out,1=in
__device__ float  g_rs [2 * N_REL * N_NODES];        // rsqrt(max(cnt,1))

// ---------------------------------------------------------------------------
// Degree histogram: one thread per (relation, edge), two int atomics.
__global__ void degree_kernel(const int* __restrict__ edges) {
    int i = blockIdx.x * blockDim.x + threadIdx.x;
    if (i >= N_REL * N_EDGES) return;
    int r = i / N_EDGES;
    int e = i - r * N_EDGES;
    int s = edges[(r * 2 + 0) * N_EDGES + e];
    int t = edges[(r * 2 + 1) * N_EDGES + e];
    atomicAdd(&g_cnt[(r * 2 + 0) * N_NODES + s], 1);
    atomicAdd(&g_cnt[(r * 2 + 1) * N_NODES + t], 1);
}

// rs = rsqrt(clip(deg, 1))
__global__ void rs_kernel() {
    int i = blockIdx.x * blockDim.x + threadIdx.x;
    if (i >= 2 * N_REL * N_NODES) return;
    g_rs[i] = rsqrtf(fmaxf((float)g_cnt[i], 1.0f));
}

// ---------------------------------------------------------------------------
// One-time conversions.
// X (f32 -> f16), 8 floats per thread.
__global__ void convert_x_kernel(const float* __restrict__ X) {
    int i = blockIdx.x * blockDim.x + threadIdx.x;
    size_t total8 = (size_t)N_NODES * D / 8;
    if ((size_t)i >= total8) return;
    const float4* src = (const float4*)X + (size_t)i * 2;
    float4 a = __ldg(src);
    float4 b = __ldg(src + 1);
    __half2 h0 = __floats2half2_rn(a.x, a.y);
    __half2 h1 = __floats2half2_rn(a.z, a.w);
    __half2 h2 = __floats2half2_rn(b.x, b.y);
    __half2 h3 = __floats2half2_rn(b.z, b.w);
    uint4 u;
    u.x = *(uint32_t*)&h0; u.y = *(uint32_t*)&h1;
    u.z = *(uint32_t*)&h2; u.w = *(uint32_t*)&h3;
    *((uint4*)g_Xh + i) = u;
}

// W[r][k][n] f32 -> g_Wt[r][n][k] f16 (transposed per relation).
__global__ void convert_w_kernel(const float* __restrict__ W) {
    int i = blockIdx.x * blockDim.x + threadIdx.x;
    if (i >= N_REL * D * D) return;
    int r = i >> 14;           // /(128*128)
    int rem = i & 16383;
    int k = rem >> 7;
    int n = rem & 127;
    g_Wt[((size_t)r * D + n) * D + k] = __float2half_rn(__ldg(&W[i]));
}

// ---------------------------------------------------------------------------
// FP16 tensor-core GEMM producing Y' = rs_out_r * (Xh @ W_r), stored fp16.
// C-block: 128 rows x 128 cols; grid.y = relation. K = 128, BK = 32.
// 256 threads = 8 warps (2 M x 4 N), warp tile 64x32, m16n8k16 f16 mma, f32 acc.
// Smem layout: half2 words, word index kw = k/2 (16 words per BK=32 row).
// Row stride 20 words -> all 32 fragment-load banks distinct.
#define GBM 128
#define GBN 128
#define GBK 32
#define SSTRIDE 20     // words (80 B, 16B-aligned chunks at kw multiples of 4)

__device__ __forceinline__ void mma_f16(float* d, const uint32_t* a,
                                        const uint32_t* b) {
    asm volatile(
        "mma.sync.aligned.m16n8k16.row.col.f32.f16.f16.f32 "
        "{%0,%1,%2,%3}, {%4,%5,%6,%7}, {%8,%9}, {%0,%1,%2,%3};"
        : "+f"(d[0]), "+f"(d[1]), "+f"(d[2]), "+f"(d[3])
        : "r"(a[0]), "r"(a[1]), "r"(a[2]), "r"(a[3]), "r"(b[0]), "r"(b[1]));
}

__global__ __launch_bounds__(256, 2)
void gemm_f16_kernel(const __half* __restrict__ Xh, const __half* __restrict__ Wt,
                     __half* __restrict__ Y) {
    __shared__ __align__(16) uint32_t As[GBM][SSTRIDE];  // [row][kw]
    __shared__ __align__(16) uint32_t Bs[GBN][SSTRIDE];  // [col][kw]

    int tid  = threadIdx.x;
    int wid  = tid >> 5;
    int lane = tid & 31;
    int lg   = lane >> 2;     // 0..7
    int lt   = lane & 3;      // 0..3
    int warp_m = wid & 1;     // 0..1 -> 64-row slab
    int warp_n = wid >> 1;    // 0..3 -> 32-col slab
    int row0 = blockIdx.x * GBM;
    int rel  = blockIdx.y;
    const __half* Bt = Wt + (size_t)rel * (D * D);   // [n][k] fp16

    float acc[4][4][4];
#pragma unroll
    for (int mi = 0; mi < 4; mi++)
#pragma unroll
        for (int ni = 0; ni < 4; ni++)
#pragma unroll
            for (int j = 0; j < 4; j++) acc[mi][ni][j] = 0.0f;

    for (int k0 = 0; k0 < D; k0 += GBK) {
        // Stage A: 128 rows x 32 halves = 512 uint4 chunks, 2 per thread.
#pragma unroll
        for (int i = 0; i < 2; i++) {
            int idx = tid + i * 256;
            int row = idx >> 2;           // 0..127
            int ch  = idx & 3;            // 16B chunk within row
            int grow = min(row0 + row, N_NODES - 1);
            uint4 u = __ldg((const uint4*)(Xh + (size_t)grow * D + k0 + ch * 8));
            *(uint4*)&As[row][ch * 4] = u;
        }
        // Stage B: 128 cols x 32 halves (k) from Wt rows.
#pragma unroll
        for (int i = 0; i < 2; i++) {
            int idx = tid + i * 256;
            int col = idx >> 2;
            int ch  = idx & 3;
            uint4 u = __ldg((const uint4*)(Bt + (size_t)col * D + k0 + ch * 8));
            *(uint4*)&Bs[col][ch * 4] = u;
        }
        __syncthreads();

#pragma unroll
        for (int ks = 0; ks < 2; ks++) {      // two k16 steps per BK=32
            int kc = ks * 8;                   // word offset
            uint32_t af[4][4];
            uint32_t bf[4][2];
#pragma unroll
            for (int mi = 0; mi < 4; mi++) {
                int base = warp_m * 64 + mi * 16;
                af[mi][0] = As[base + lg    ][kc + lt    ];
                af[mi][1] = As[base + lg + 8][kc + lt    ];
                af[mi][2] = As[base + lg    ][kc + lt + 4];
                af[mi][3] = As[base + lg + 8][kc + lt + 4];
            }
#pragma unroll
            for (int ni = 0; ni < 4; ni++) {
                int col = warp_n * 32 + ni * 8 + lg;
                bf[ni][0] = Bs[col][kc + lt    ];
                bf[ni][1] = Bs[col][kc + lt + 4];
            }
#pragma unroll
            for (int mi = 0; mi < 4; mi++)
#pragma unroll
                for (int ni = 0; ni < 4; ni++)
                    mma_f16(acc[mi][ni], af[mi], bf[ni]);
        }
        __syncthreads();
    }

    // Epilogue: scale by rs_out_rel[row], convert fp16, store to Y.
    // c0,c1 -> (row, 2lt),(row,2lt+1); c2,c3 -> row+8.
    const float* rs_out = g_rs + (size_t)(rel * 2 + 0) * N_NODES;
#pragma unroll
    for (int mi = 0; mi < 4; mi++) {
        int r = row0 + warp_m * 64 + mi * 16 + lg;
        float s0 = (r     < N_NODES) ? __ldg(&rs_out[r])     : 0.0f;
        float s1 = (r + 8 < N_NODES) ? __ldg(&rs_out[r + 8]) : 0.0f;
#pragma unroll
        for (int ni = 0; ni < 4; ni++) {
            int c = warp_n * 32 + ni * 8 + 2 * lt;
            if (r < N_NODES) {
                __half2 h = __floats2half2_rn(acc[mi][ni][0] * s0,
                                              acc[mi][ni][1] * s0);
                *(__half2*)(Y + (size_t)r * KTOT + rel * D + c) = h;
            }
            if (r + 8 < N_NODES) {
                __half2 h = __floats2half2_rn(acc[mi][ni][2] * s1,
                                              acc[mi][ni][3] * s1);
                *(__half2*)(Y + (size_t)(r + 8) * KTOT + rel * D + c) = h;
            }
        }
    }
}

// ---------------------------------------------------------------------------
// Scatter, warp-batched: each warp owns 32 consecutive edges of one relation.
#define EDGES_PER_WARP 32
#define WARPS_PER_REL  (N_EDGES / EDGES_PER_WARP)   // 18750

__global__ __launch_bounds__(256)
void scatter_kernel(const int* __restrict__ edges,
                    const __half* __restrict__ Y,
                    float* __restrict__ out) {
    int gtid = blockIdx.x * blockDim.x + threadIdx.x;
    int warp = gtid >> 5;
    if (warp >= N_REL * WARPS_PER_REL) return;
    int lane = threadIdx.x & 31;
    int r  = warp / WARPS_PER_REL;
    int e0 = (warp - r * WARPS_PER_REL) * EDGES_PER_WARP;
    int e  = e0 + lane;

    int   s_l = __ldg(&edges[(r * 2 + 0) * N_EDGES + e]);
    int   t_l = __ldg(&edges[(r * 2 + 1) * N_EDGES + e]);
    float c_l = __ldg(&g_rs[(r * 2 + 1) * N_NODES + t_l]);

    const __half* Yr = Y + (size_t)r * D;

#pragma unroll
    for (int i = 0; i < EDGES_PER_WARP; i++) {
        int   si = __shfl_sync(0xffffffffu, s_l, i);
        int   ti = __shfl_sync(0xffffffffu, t_l, i);
        float ci = __shfl_sync(0xffffffffu, c_l, i);

        uint2 v = __ldg((const uint2*)(Yr + (size_t)si * KTOT) + lane);
        float2 f0 = __half22float2(*(__half2*)&v.x);
        float2 f1 = __half22float2(*(__half2*)&v.y);

        float* dst = out + (size_t)ti * D + lane * 4;
        asm volatile("red.global.add.v4.f32 [%0], {%1, %2, %3, %4};"
                     :: "l"(dst),
                        "f"(f0.x * ci), "f"(f0.y * ci),
                        "f"(f1.x * ci), "f"(f1.y * ci)
                     : "memory");
    }
}

// ---------------------------------------------------------------------------
extern "C" void kernel_launch(void* const* d_in, const int* in_sizes, int n_in,
                              void* d_out, int out_size) {
    const int*   edges = (const int*)d_in[0];    // [4, 2, 600000] int32
    const float* X     = (const float*)d_in[1];  // [100000, 128] f32
    const float* W     = (const float*)d_in[2];  // [4, 128, 128] f32
    float*       out   = (float*)d_out;          // [100000, 128] f32

    void* cntp = nullptr;
    void* yp = nullptr;
    void* xhp = nullptr;
    void* wtp = nullptr;
    cudaGetSymbolAddress(&cntp, g_cnt);
    cudaGetSymbolAddress(&yp, g_Y);
    cudaGetSymbolAddress(&xhp, g_Xh);
    cudaGetSymbolAddress(&wtp, g_Wt);

    cudaMemsetAsync(cntp, 0, sizeof(int) * 2 * N_REL * N_NODES, 0);
    cudaMemsetAsync(out, 0, sizeof(float) * (size_t)N_NODES * D, 0);

    {
        int total = N_REL * N_EDGES;
        degree_kernel<<<(total + 255) / 256, 256>>>(edges);
    }
    {
        int total = 2 * N_REL * N_NODES;
        rs_kernel<<<(total + 255) / 256, 256>>>();
    }
    {
        size_t total8 = (size_t)N_NODES * D / 8;
        convert_x_kernel<<<(int)((total8 + 255) / 256), 256>>>(X);
    }
    {
        int total = N_REL * D * D;
        convert_w_kernel<<<(total + 255) / 256, 256>>>(W);
    }
    {
        dim3 grid((N_NODES + GBM - 1) / GBM, N_REL);   // (782, 4)
        gemm_f16_kernel<<<grid, 256>>>((const __half*)xhp, (const __half*)wtp,
                                       (__half*)yp);
    }
    {
        int total_warps = N_REL * WARPS_PER_REL;       // 75000
        long long threads = (long long)total_warps * 32;
        int blocks = (int)((threads + 255) / 256);
        scatter_kernel<<<blocks, 256>>>(edges, (const __half*)yp, out);
    }
}